// round 14
// baseline (speedup 1.0000x reference)
#include <cuda_runtime.h>
#include <cuda_fp16.h>

// HierarchicalBG: equirect unwrap -> bilinear gather from two (16,H,W) grids
// -> MLP 16->128 (relu) -> 128->3 (softplus).  B = 1048576, out (B,3) f32.
//
// R13: gather kernel is FMA-ISSUE-bound (not memory). Convert gather
// accumulation and the 16->128 MLP stage to packed HFMA2 (2 FMA/issue),
// keep the final 128->3 stage in fp32. Grids stored fp16 channel-interleaved
// ([y][x][16], 32 B/texel) by a per-launch transpose.

#define H0 512
#define W0 1024
#define H1 2048
#define W1 4096

__device__ __half g_t0h[16u * H0 * W0];   //  16.8 MB interleaved m0 (fp16)
__device__ __half g_t1h[16u * H1 * W1];   // 268.4 MB interleaved m1 (fp16)

// ---------- transpose: [16][HW] fp32 -> [HW][16] fp16, 4 pixels/thread ----------
__global__ __launch_bounds__(256)
void transpose_kernel(const float* __restrict__ src, __half* __restrict__ dst,
                      int HW) {
    int p4 = (blockIdx.x * blockDim.x + threadIdx.x) * 4;
    if (p4 >= HW) return;
    __half2 h[4][8];                       // [pixel][channel-pair]
    #pragma unroll
    for (int r = 0; r < 8; ++r) {
        float4 a = *(const float4*)(src + (size_t)(2 * r)     * HW + p4);
        float4 b = *(const float4*)(src + (size_t)(2 * r + 1) * HW + p4);
        h[0][r] = __floats2half2_rn(a.x, b.x);
        h[1][r] = __floats2half2_rn(a.y, b.y);
        h[2][r] = __floats2half2_rn(a.z, b.z);
        h[3][r] = __floats2half2_rn(a.w, b.w);
    }
    uint4* d = (uint4*)(dst + (size_t)p4 * 16);
    #pragma unroll
    for (int t = 0; t < 4; ++t) {
        const uint4* hs = (const uint4*)h[t];
        d[2 * t]     = hs[0];
        d[2 * t + 1] = hs[1];
    }
}

// ---------- gather one corner: 16 fp16 ch = one LDG.128 pair, HFMA2 accum ----------
static __device__ __forceinline__ void corner_add(const __half* __restrict__ g,
                                                  int H, int W,
                                                  int x, int y, float w,
                                                  __half2* emb8) {
    bool valid = (x >= 0) && (x < W) && (y >= 0) && (y < H);
    w = valid ? w : 0.0f;
    __half2 wh = __float2half2_rn(w);
    int xc = min(max(x, 0), W - 1);
    int yc = min(max(y, 0), H - 1);
    const uint4* p = (const uint4*)(g + (size_t)(yc * W + xc) * 16);
    uint4 a = p[0];
    uint4 b = p[1];
    const __half2* ha = (const __half2*)&a;
    const __half2* hb = (const __half2*)&b;
    #pragma unroll
    for (int k = 0; k < 4; ++k) emb8[k]     = __hfma2(wh, ha[k], emb8[k]);
    #pragma unroll
    for (int k = 0; k < 4; ++k) emb8[4 + k] = __hfma2(wh, hb[k], emb8[4 + k]);
}

static __device__ __forceinline__ void sample_add(const __half* __restrict__ g,
                                                  int H, int W,
                                                  float gx, float gy,
                                                  float scale, __half2* emb8) {
    float px = ((gx + 1.0f) * (float)W - 1.0f) * 0.5f;
    float py = ((gy + 1.0f) * (float)H - 1.0f) * 0.5f;
    float x0f = floorf(px), y0f = floorf(py);
    float wx1 = px - x0f, wy1 = py - y0f;
    float wx0 = 1.0f - wx1, wy0 = 1.0f - wy1;
    int x0 = (int)x0f, y0 = (int)y0f;
    corner_add(g, H, W, x0,     y0,     scale * wx0 * wy0, emb8);
    corner_add(g, H, W, x0 + 1, y0,     scale * wx1 * wy0, emb8);
    corner_add(g, H, W, x0,     y0 + 1, scale * wx0 * wy1, emb8);
    corner_add(g, H, W, x0 + 1, y0 + 1, scale * wx1 * wy1, emb8);
}

static __device__ __forceinline__ float softplusf(float x) {
    return fmaxf(x, 0.0f) + log1pf(expf(-fabsf(x)));
}

__global__ __launch_bounds__(256, 3)
void hierarchical_bg_kernel(const float* __restrict__ vd,
                            const float* __restrict__ w1,
                            const float* __restrict__ w2,
                            float* __restrict__ out, int n) {
    // s_w1u[k*16 + q] = uint4 of 4 half2 = w1[k][8q .. 8q+7]
    __shared__ uint4  s_w1u[256];
    // s_w2v[o*32 + g] = float4 of w2[4g..4g+3][o]
    __shared__ float4 s_w2v[96];

    {
        int t = threadIdx.x;               // 256 threads: one (k,q) each
        int k = t >> 4, q = t & 15;
        const float* wr = w1 + k * 128 + q * 8;
        __half2 hp[4];
        #pragma unroll
        for (int j = 0; j < 4; ++j)
            hp[j] = __floats2half2_rn(wr[2 * j], wr[2 * j + 1]);
        s_w1u[k * 16 + q] = *(const uint4*)hp;

        float* s2 = (float*)s_w2v;
        for (int u = t; u < 384; u += blockDim.x) {
            int o = u >> 7;
            int j = u & 127;
            s2[u] = w2[j * 3 + o];
        }
    }
    __syncthreads();

    int i = blockIdx.x * blockDim.x + threadIdx.x;
    if (i >= n) return;

    // --- unwrap_equirect ---
    float vx = vd[3 * i + 0];
    float vy = vd[3 * i + 1];
    float vz = vd[3 * i + 2];
    float inv = 1.0f / (sqrtf(vx * vx + vy * vy + vz * vz) + 1e-8f);
    float dx = vx * inv, dy = vy * inv, dz = vz * inv;
    const float INV_PI = 0.318309886183790671538f;
    float gx = atan2f(dx, dy) * INV_PI;
    float gy = acosf(fminf(fmaxf(dz, -1.0f), 1.0f)) * (2.0f * INV_PI) - 1.0f;

    // --- gathers (half2 accumulate) ---
    __half2 emb8[8];
    #pragma unroll
    for (int r = 0; r < 8; ++r) emb8[r] = __float2half2_rn(0.0f);
    sample_add(g_t0h, H0, W0, gx, gy, 1.0f, emb8);
    sample_add(g_t1h, H1, W1, gx, gy, 0.5f, emb8);

    // broadcast each channel into a half2
    __half2 eb[16];
    #pragma unroll
    for (int t = 0; t < 8; ++t) {
        eb[2 * t]     = __low2half2(emb8[t]);
        eb[2 * t + 1] = __high2half2(emb8[t]);
    }

    // --- MLP: h = relu(emb @ w1) in HFMA2; out = softplus(h @ w2) in fp32 ---
    float a0 = 0.0f, a1 = 0.0f, a2 = 0.0f;
    const __half2 zero = __float2half2_rn(0.0f);
    #pragma unroll
    for (int q = 0; q < 16; ++q) {         // 8 hidden units per iteration
        __half2 h0 = zero, h1 = zero, h2v = zero, h3 = zero;
        #pragma unroll
        for (int k = 0; k < 16; ++k) {
            uint4 wv = s_w1u[k * 16 + q];
            const __half2* wh = (const __half2*)&wv;
            h0  = __hfma2(eb[k], wh[0], h0);
            h1  = __hfma2(eb[k], wh[1], h1);
            h2v = __hfma2(eb[k], wh[2], h2v);
            h3  = __hfma2(eb[k], wh[3], h3);
        }
        h0  = __hmax2(h0, zero);
        h1  = __hmax2(h1, zero);
        h2v = __hmax2(h2v, zero);
        h3  = __hmax2(h3, zero);
        float2 f0 = __half22float2(h0);
        float2 f1 = __half22float2(h1);
        float2 f2 = __half22float2(h2v);
        float2 f3 = __half22float2(h3);
        // j = 8q..8q+7 -> groups g=2q (f0,f1) and g=2q+1 (f2,f3)
        float4 wa0 = s_w2v[2 * q],      wa1 = s_w2v[2 * q + 1];
        float4 wb0 = s_w2v[32 + 2 * q], wb1 = s_w2v[32 + 2 * q + 1];
        float4 wc0 = s_w2v[64 + 2 * q], wc1 = s_w2v[64 + 2 * q + 1];
        a0 = fmaf(f0.x, wa0.x, fmaf(f0.y, wa0.y, fmaf(f1.x, wa0.z, fmaf(f1.y, wa0.w, a0))));
        a0 = fmaf(f2.x, wa1.x, fmaf(f2.y, wa1.y, fmaf(f3.x, wa1.z, fmaf(f3.y, wa1.w, a0))));
        a1 = fmaf(f0.x, wb0.x, fmaf(f0.y, wb0.y, fmaf(f1.x, wb0.z, fmaf(f1.y, wb0.w, a1))));
        a1 = fmaf(f2.x, wb1.x, fmaf(f2.y, wb1.y, fmaf(f3.x, wb1.z, fmaf(f3.y, wb1.w, a1))));
        a2 = fmaf(f0.x, wc0.x, fmaf(f0.y, wc0.y, fmaf(f1.x, wc0.z, fmaf(f1.y, wc0.w, a2))));
        a2 = fmaf(f2.x, wc1.x, fmaf(f2.y, wc1.y, fmaf(f3.x, wc1.z, fmaf(f3.y, wc1.w, a2))));
    }

    out[3 * i + 0] = softplusf(a0);
    out[3 * i + 1] = softplusf(a1);
    out[3 * i + 2] = softplusf(a2);
}

extern "C" void kernel_launch(void* const* d_in, const int* in_sizes, int n_in,
                              void* d_out, int out_size) {
    const float* vd = (const float*)d_in[0];   // viewdirs (B,3)
    const float* m0 = (const float*)d_in[1];   // bg_mat0 (1,16,512,1024)
    const float* m1 = (const float*)d_in[2];   // bg_mat1 (1,16,2048,4096)
    const float* w1 = (const float*)d_in[3];   // (16,128)
    const float* w2 = (const float*)d_in[4];   // (128,3)
    float* out = (float*)d_out;

    __half* t0;
    __half* t1;
    cudaGetSymbolAddress((void**)&t0, g_t0h);
    cudaGetSymbolAddress((void**)&t1, g_t1h);

    const int HW0 = H0 * W0;
    const int HW1 = H1 * W1;
    transpose_kernel<<<HW0 / 4 / 256, 256>>>(m0, t0, HW0);
    transpose_kernel<<<HW1 / 4 / 256, 256>>>(m1, t1, HW1);

    int n = in_sizes[0] / 3;
    const int threads = 256;
    int blocks = (n + threads - 1) / threads;
    hierarchical_bg_kernel<<<blocks, threads>>>(vd, w1, w2, out, n);
}

// round 15
// speedup vs baseline: 1.1327x; 1.1327x over previous
#include <cuda_runtime.h>
#include <cuda_fp16.h>

// HierarchicalBG: equirect unwrap -> bilinear gather from two (16,H,W) grids
// -> MLP 16->128 (relu) -> 128->3 (softplus).  B = 1048576, out (B,3) f32.
//
// R15: (a) transpose uses streaming cache hints (__ldcs reads; __stcs writes
// for the 268MB m1 output so it doesn't flush L2; m0's 16.8MB output kept
// L2-resident and written last). (b) gather kernel prefetches all 8 m1
// corner texels (DRAM latency) before doing the m0 sample (L2 hits), so only
// one DRAM round-trip is exposed per point.

#define H0 512
#define W0 1024
#define H1 2048
#define W1 4096

__device__ __half g_t0h[16u * H0 * W0];   //  16.8 MB interleaved m0 (fp16)
__device__ __half g_t1h[16u * H1 * W1];   // 268.4 MB interleaved m1 (fp16)

// ---------- transpose: [16][HW] fp32 -> [HW][16] fp16, 4 pixels/thread ----------
__global__ __launch_bounds__(256)
void transpose_kernel(const float* __restrict__ src, __half* __restrict__ dst,
                      int HW, int stream_out) {
    int p4 = (blockIdx.x * blockDim.x + threadIdx.x) * 4;
    if (p4 >= HW) return;
    __half2 h[4][8];                       // [pixel][channel-pair]
    #pragma unroll
    for (int r = 0; r < 8; ++r) {
        float4 a = __ldcs((const float4*)(src + (size_t)(2 * r)     * HW + p4));
        float4 b = __ldcs((const float4*)(src + (size_t)(2 * r + 1) * HW + p4));
        h[0][r] = __floats2half2_rn(a.x, b.x);
        h[1][r] = __floats2half2_rn(a.y, b.y);
        h[2][r] = __floats2half2_rn(a.z, b.z);
        h[3][r] = __floats2half2_rn(a.w, b.w);
    }
    float4* d = (float4*)(dst + (size_t)p4 * 16);
    if (stream_out) {
        #pragma unroll
        for (int t = 0; t < 4; ++t) {
            const float4* hs = (const float4*)h[t];
            __stcs(d + 2 * t,     hs[0]);
            __stcs(d + 2 * t + 1, hs[1]);
        }
    } else {
        #pragma unroll
        for (int t = 0; t < 4; ++t) {
            const float4* hs = (const float4*)h[t];
            d[2 * t]     = hs[0];
            d[2 * t + 1] = hs[1];
        }
    }
}

// ---------- corner helpers ----------
static __device__ __forceinline__ float corner_w(int x, int y, int H, int W,
                                                 float w) {
    bool valid = (x >= 0) && (x < W) && (y >= 0) && (y < H);
    return valid ? w : 0.0f;
}

static __device__ __forceinline__ const uint4* corner_ptr(
        const __half* __restrict__ g, int x, int y, int H, int W) {
    int xc = min(max(x, 0), W - 1);
    int yc = min(max(y, 0), H - 1);
    return (const uint4*)(g + (size_t)(yc * W + xc) * 16);
}

static __device__ __forceinline__ void accum_texel(const uint4& a,
                                                   const uint4& b,
                                                   __half2 wh, __half2* emb8) {
    const __half2* ha = (const __half2*)&a;
    const __half2* hb = (const __half2*)&b;
    #pragma unroll
    for (int k = 0; k < 4; ++k) emb8[k]     = __hfma2(wh, ha[k], emb8[k]);
    #pragma unroll
    for (int k = 0; k < 4; ++k) emb8[4 + k] = __hfma2(wh, hb[k], emb8[4 + k]);
}

static __device__ __forceinline__ float softplusf(float x) {
    return fmaxf(x, 0.0f) + log1pf(expf(-fabsf(x)));
}

__global__ __launch_bounds__(256, 3)
void hierarchical_bg_kernel(const float* __restrict__ vd,
                            const float* __restrict__ w1,
                            const float* __restrict__ w2,
                            float* __restrict__ out, int n) {
    // s_w1u[k*16 + q] = uint4 of 4 half2 = w1[k][8q .. 8q+7]
    __shared__ uint4  s_w1u[256];
    // s_w2v[o*32 + g] = float4 of w2[4g..4g+3][o]
    __shared__ float4 s_w2v[96];

    {
        int t = threadIdx.x;               // 256 threads: one (k,q) each
        int k = t >> 4, q = t & 15;
        const float* wr = w1 + k * 128 + q * 8;
        __half2 hp[4];
        #pragma unroll
        for (int j = 0; j < 4; ++j)
            hp[j] = __floats2half2_rn(wr[2 * j], wr[2 * j + 1]);
        s_w1u[k * 16 + q] = *(const uint4*)hp;

        float* s2 = (float*)s_w2v;
        for (int u = t; u < 384; u += blockDim.x) {
            int o = u >> 7;
            int j = u & 127;
            s2[u] = w2[j * 3 + o];
        }
    }
    __syncthreads();

    int i = blockIdx.x * blockDim.x + threadIdx.x;
    if (i >= n) return;

    // --- unwrap_equirect ---
    float vx = vd[3 * i + 0];
    float vy = vd[3 * i + 1];
    float vz = vd[3 * i + 2];
    float inv = 1.0f / (sqrtf(vx * vx + vy * vy + vz * vz) + 1e-8f);
    float dx = vx * inv, dy = vy * inv, dz = vz * inv;
    const float INV_PI = 0.318309886183790671538f;
    float gx = atan2f(dx, dy) * INV_PI;
    float gy = acosf(fminf(fmaxf(dz, -1.0f), 1.0f)) * (2.0f * INV_PI) - 1.0f;

    // ---- m1 corner addresses + PREFETCH (DRAM, long latency) ----
    float px1 = ((gx + 1.0f) * (float)W1 - 1.0f) * 0.5f;
    float py1 = ((gy + 1.0f) * (float)H1 - 1.0f) * 0.5f;
    float x1f = floorf(px1), y1f = floorf(py1);
    float ax1 = px1 - x1f, ay1 = py1 - y1f;
    int x1 = (int)x1f, y1 = (int)y1f;
    const uint4* q00 = corner_ptr(g_t1h, x1,     y1,     H1, W1);
    const uint4* q10 = corner_ptr(g_t1h, x1 + 1, y1,     H1, W1);
    const uint4* q01 = corner_ptr(g_t1h, x1,     y1 + 1, H1, W1);
    const uint4* q11 = corner_ptr(g_t1h, x1 + 1, y1 + 1, H1, W1);
    uint4 u00a = __ldg(q00), u00b = __ldg(q00 + 1);
    uint4 u10a = __ldg(q10), u10b = __ldg(q10 + 1);
    uint4 u01a = __ldg(q01), u01b = __ldg(q01 + 1);
    uint4 u11a = __ldg(q11), u11b = __ldg(q11 + 1);

    // m1 weights (scale 0.5 folded in)
    float m1w00 = corner_w(x1,     y1,     H1, W1, 0.5f * (1.0f - ax1) * (1.0f - ay1));
    float m1w10 = corner_w(x1 + 1, y1,     H1, W1, 0.5f * ax1          * (1.0f - ay1));
    float m1w01 = corner_w(x1,     y1 + 1, H1, W1, 0.5f * (1.0f - ax1) * ay1);
    float m1w11 = corner_w(x1 + 1, y1 + 1, H1, W1, 0.5f * ax1          * ay1);

    // ---- m0 sample (L2-resident, short latency) while m1 is in flight ----
    __half2 emb8[8];
    #pragma unroll
    for (int r = 0; r < 8; ++r) emb8[r] = __float2half2_rn(0.0f);
    {
        float px = ((gx + 1.0f) * (float)W0 - 1.0f) * 0.5f;
        float py = ((gy + 1.0f) * (float)H0 - 1.0f) * 0.5f;
        float x0f = floorf(px), y0f = floorf(py);
        float ax = px - x0f, ay = py - y0f;
        int x0 = (int)x0f, y0 = (int)y0f;
        const uint4* p00 = corner_ptr(g_t0h, x0,     y0,     H0, W0);
        const uint4* p10 = corner_ptr(g_t0h, x0 + 1, y0,     H0, W0);
        const uint4* p01 = corner_ptr(g_t0h, x0,     y0 + 1, H0, W0);
        const uint4* p11 = corner_ptr(g_t0h, x0 + 1, y0 + 1, H0, W0);
        uint4 v00a = __ldg(p00), v00b = __ldg(p00 + 1);
        uint4 v10a = __ldg(p10), v10b = __ldg(p10 + 1);
        uint4 v01a = __ldg(p01), v01b = __ldg(p01 + 1);
        uint4 v11a = __ldg(p11), v11b = __ldg(p11 + 1);
        __half2 h00 = __float2half2_rn(corner_w(x0,     y0,     H0, W0, (1.0f - ax) * (1.0f - ay)));
        __half2 h10 = __float2half2_rn(corner_w(x0 + 1, y0,     H0, W0, ax          * (1.0f - ay)));
        __half2 h01 = __float2half2_rn(corner_w(x0,     y0 + 1, H0, W0, (1.0f - ax) * ay));
        __half2 h11 = __float2half2_rn(corner_w(x0 + 1, y0 + 1, H0, W0, ax          * ay));
        accum_texel(v00a, v00b, h00, emb8);
        accum_texel(v10a, v10b, h10, emb8);
        accum_texel(v01a, v01b, h01, emb8);
        accum_texel(v11a, v11b, h11, emb8);
    }

    // ---- consume m1 ----
    accum_texel(u00a, u00b, __float2half2_rn(m1w00), emb8);
    accum_texel(u10a, u10b, __float2half2_rn(m1w10), emb8);
    accum_texel(u01a, u01b, __float2half2_rn(m1w01), emb8);
    accum_texel(u11a, u11b, __float2half2_rn(m1w11), emb8);

    // broadcast each channel into a half2
    __half2 eb[16];
    #pragma unroll
    for (int t = 0; t < 8; ++t) {
        eb[2 * t]     = __low2half2(emb8[t]);
        eb[2 * t + 1] = __high2half2(emb8[t]);
    }

    // --- MLP: h = relu(emb @ w1) in HFMA2; out = softplus(h @ w2) in fp32 ---
    float a0 = 0.0f, a1 = 0.0f, a2 = 0.0f;
    const __half2 zero = __float2half2_rn(0.0f);
    #pragma unroll
    for (int q = 0; q < 16; ++q) {         // 8 hidden units per iteration
        __half2 h0 = zero, h1 = zero, h2v = zero, h3 = zero;
        #pragma unroll
        for (int k = 0; k < 16; ++k) {
            uint4 wv = s_w1u[k * 16 + q];
            const __half2* wh = (const __half2*)&wv;
            h0  = __hfma2(eb[k], wh[0], h0);
            h1  = __hfma2(eb[k], wh[1], h1);
            h2v = __hfma2(eb[k], wh[2], h2v);
            h3  = __hfma2(eb[k], wh[3], h3);
        }
        h0  = __hmax2(h0, zero);
        h1  = __hmax2(h1, zero);
        h2v = __hmax2(h2v, zero);
        h3  = __hmax2(h3, zero);
        float2 f0 = __half22float2(h0);
        float2 f1 = __half22float2(h1);
        float2 f2 = __half22float2(h2v);
        float2 f3 = __half22float2(h3);
        float4 wa0 = s_w2v[2 * q],      wa1 = s_w2v[2 * q + 1];
        float4 wb0 = s_w2v[32 + 2 * q], wb1 = s_w2v[32 + 2 * q + 1];
        float4 wc0 = s_w2v[64 + 2 * q], wc1 = s_w2v[64 + 2 * q + 1];
        a0 = fmaf(f0.x, wa0.x, fmaf(f0.y, wa0.y, fmaf(f1.x, wa0.z, fmaf(f1.y, wa0.w, a0))));
        a0 = fmaf(f2.x, wa1.x, fmaf(f2.y, wa1.y, fmaf(f3.x, wa1.z, fmaf(f3.y, wa1.w, a0))));
        a1 = fmaf(f0.x, wb0.x, fmaf(f0.y, wb0.y, fmaf(f1.x, wb0.z, fmaf(f1.y, wb0.w, a1))));
        a1 = fmaf(f2.x, wb1.x, fmaf(f2.y, wb1.y, fmaf(f3.x, wb1.z, fmaf(f3.y, wb1.w, a1))));
        a2 = fmaf(f0.x, wc0.x, fmaf(f0.y, wc0.y, fmaf(f1.x, wc0.z, fmaf(f1.y, wc0.w, a2))));
        a2 = fmaf(f2.x, wc1.x, fmaf(f2.y, wc1.y, fmaf(f3.x, wc1.z, fmaf(f3.y, wc1.w, a2))));
    }

    out[3 * i + 0] = softplusf(a0);
    out[3 * i + 1] = softplusf(a1);
    out[3 * i + 2] = softplusf(a2);
}

extern "C" void kernel_launch(void* const* d_in, const int* in_sizes, int n_in,
                              void* d_out, int out_size) {
    const float* vd = (const float*)d_in[0];   // viewdirs (B,3)
    const float* m0 = (const float*)d_in[1];   // bg_mat0 (1,16,512,1024)
    const float* m1 = (const float*)d_in[2];   // bg_mat1 (1,16,2048,4096)
    const float* w1 = (const float*)d_in[3];   // (16,128)
    const float* w2 = (const float*)d_in[4];   // (128,3)
    float* out = (float*)d_out;

    __half* t0;
    __half* t1;
    cudaGetSymbolAddress((void**)&t0, g_t0h);
    cudaGetSymbolAddress((void**)&t1, g_t1h);

    const int HW0 = H0 * W0;
    const int HW1 = H1 * W1;
    // m1 first (streamed writes, bypass L2), m0 last (L2-resident for gather)
    transpose_kernel<<<HW1 / 4 / 256, 256>>>(m1, t1, HW1, 1);
    transpose_kernel<<<HW0 / 4 / 256, 256>>>(m0, t0, HW0, 0);

    int n = in_sizes[0] / 3;
    const int threads = 256;
    int blocks = (n + threads - 1) / threads;
    hierarchical_bg_kernel<<<blocks, threads>>>(vd, w1, w2, out, n);
}

// round 16
// speedup vs baseline: 1.1382x; 1.0049x over previous
#include <cuda_runtime.h>
#include <cuda_fp16.h>

// HierarchicalBG: equirect unwrap -> bilinear gather from two (16,H,W) grids
// -> MLP 16->128 (relu) -> 128->3 (softplus).  B = 1048576, out (B,3) f32.
//
// R15: (a) transpose uses streaming cache hints (__ldcs reads; __stcs writes
// for the 268MB m1 output so it doesn't flush L2; m0's 16.8MB output kept
// L2-resident and written last). (b) gather kernel prefetches all 8 m1
// corner texels (DRAM latency) before doing the m0 sample (L2 hits), so only
// one DRAM round-trip is exposed per point.

#define H0 512
#define W0 1024
#define H1 2048
#define W1 4096

__device__ __half g_t0h[16u * H0 * W0];   //  16.8 MB interleaved m0 (fp16)
__device__ __half g_t1h[16u * H1 * W1];   // 268.4 MB interleaved m1 (fp16)

// ---------- transpose: [16][HW] fp32 -> [HW][16] fp16, 4 pixels/thread ----------
__global__ __launch_bounds__(256)
void transpose_kernel(const float* __restrict__ src, __half* __restrict__ dst,
                      int HW, int stream_out) {
    int p4 = (blockIdx.x * blockDim.x + threadIdx.x) * 4;
    if (p4 >= HW) return;
    __half2 h[4][8];                       // [pixel][channel-pair]
    #pragma unroll
    for (int r = 0; r < 8; ++r) {
        float4 a = __ldcs((const float4*)(src + (size_t)(2 * r)     * HW + p4));
        float4 b = __ldcs((const float4*)(src + (size_t)(2 * r + 1) * HW + p4));
        h[0][r] = __floats2half2_rn(a.x, b.x);
        h[1][r] = __floats2half2_rn(a.y, b.y);
        h[2][r] = __floats2half2_rn(a.z, b.z);
        h[3][r] = __floats2half2_rn(a.w, b.w);
    }
    float4* d = (float4*)(dst + (size_t)p4 * 16);
    if (stream_out) {
        #pragma unroll
        for (int t = 0; t < 4; ++t) {
            const float4* hs = (const float4*)h[t];
            __stcs(d + 2 * t,     hs[0]);
            __stcs(d + 2 * t + 1, hs[1]);
        }
    } else {
        #pragma unroll
        for (int t = 0; t < 4; ++t) {
            const float4* hs = (const float4*)h[t];
            d[2 * t]     = hs[0];
            d[2 * t + 1] = hs[1];
        }
    }
}

// ---------- corner helpers ----------
static __device__ __forceinline__ float corner_w(int x, int y, int H, int W,
                                                 float w) {
    bool valid = (x >= 0) && (x < W) && (y >= 0) && (y < H);
    return valid ? w : 0.0f;
}

static __device__ __forceinline__ const uint4* corner_ptr(
        const __half* __restrict__ g, int x, int y, int H, int W) {
    int xc = min(max(x, 0), W - 1);
    int yc = min(max(y, 0), H - 1);
    return (const uint4*)(g + (size_t)(yc * W + xc) * 16);
}

static __device__ __forceinline__ void accum_texel(const uint4& a,
                                                   const uint4& b,
                                                   __half2 wh, __half2* emb8) {
    const __half2* ha = (const __half2*)&a;
    const __half2* hb = (const __half2*)&b;
    #pragma unroll
    for (int k = 0; k < 4; ++k) emb8[k]     = __hfma2(wh, ha[k], emb8[k]);
    #pragma unroll
    for (int k = 0; k < 4; ++k) emb8[4 + k] = __hfma2(wh, hb[k], emb8[4 + k]);
}

static __device__ __forceinline__ float softplusf(float x) {
    return fmaxf(x, 0.0f) + log1pf(expf(-fabsf(x)));
}

__global__ __launch_bounds__(256, 3)
void hierarchical_bg_kernel(const float* __restrict__ vd,
                            const float* __restrict__ w1,
                            const float* __restrict__ w2,
                            float* __restrict__ out, int n) {
    // s_w1u[k*16 + q] = uint4 of 4 half2 = w1[k][8q .. 8q+7]
    __shared__ uint4  s_w1u[256];
    // s_w2v[o*32 + g] = float4 of w2[4g..4g+3][o]
    __shared__ float4 s_w2v[96];

    {
        int t = threadIdx.x;               // 256 threads: one (k,q) each
        int k = t >> 4, q = t & 15;
        const float* wr = w1 + k * 128 + q * 8;
        __half2 hp[4];
        #pragma unroll
        for (int j = 0; j < 4; ++j)
            hp[j] = __floats2half2_rn(wr[2 * j], wr[2 * j + 1]);
        s_w1u[k * 16 + q] = *(const uint4*)hp;

        float* s2 = (float*)s_w2v;
        for (int u = t; u < 384; u += blockDim.x) {
            int o = u >> 7;
            int j = u & 127;
            s2[u] = w2[j * 3 + o];
        }
    }
    __syncthreads();

    int i = blockIdx.x * blockDim.x + threadIdx.x;
    if (i >= n) return;

    // --- unwrap_equirect ---
    float vx = vd[3 * i + 0];
    float vy = vd[3 * i + 1];
    float vz = vd[3 * i + 2];
    float inv = 1.0f / (sqrtf(vx * vx + vy * vy + vz * vz) + 1e-8f);
    float dx = vx * inv, dy = vy * inv, dz = vz * inv;
    const float INV_PI = 0.318309886183790671538f;
    float gx = atan2f(dx, dy) * INV_PI;
    float gy = acosf(fminf(fmaxf(dz, -1.0f), 1.0f)) * (2.0f * INV_PI) - 1.0f;

    // ---- m1 corner addresses + PREFETCH (DRAM, long latency) ----
    float px1 = ((gx + 1.0f) * (float)W1 - 1.0f) * 0.5f;
    float py1 = ((gy + 1.0f) * (float)H1 - 1.0f) * 0.5f;
    float x1f = floorf(px1), y1f = floorf(py1);
    float ax1 = px1 - x1f, ay1 = py1 - y1f;
    int x1 = (int)x1f, y1 = (int)y1f;
    const uint4* q00 = corner_ptr(g_t1h, x1,     y1,     H1, W1);
    const uint4* q10 = corner_ptr(g_t1h, x1 + 1, y1,     H1, W1);
    const uint4* q01 = corner_ptr(g_t1h, x1,     y1 + 1, H1, W1);
    const uint4* q11 = corner_ptr(g_t1h, x1 + 1, y1 + 1, H1, W1);
    uint4 u00a = __ldg(q00), u00b = __ldg(q00 + 1);
    uint4 u10a = __ldg(q10), u10b = __ldg(q10 + 1);
    uint4 u01a = __ldg(q01), u01b = __ldg(q01 + 1);
    uint4 u11a = __ldg(q11), u11b = __ldg(q11 + 1);

    // m1 weights (scale 0.5 folded in)
    float m1w00 = corner_w(x1,     y1,     H1, W1, 0.5f * (1.0f - ax1) * (1.0f - ay1));
    float m1w10 = corner_w(x1 + 1, y1,     H1, W1, 0.5f * ax1          * (1.0f - ay1));
    float m1w01 = corner_w(x1,     y1 + 1, H1, W1, 0.5f * (1.0f - ax1) * ay1);
    float m1w11 = corner_w(x1 + 1, y1 + 1, H1, W1, 0.5f * ax1          * ay1);

    // ---- m0 sample (L2-resident, short latency) while m1 is in flight ----
    __half2 emb8[8];
    #pragma unroll
    for (int r = 0; r < 8; ++r) emb8[r] = __float2half2_rn(0.0f);
    {
        float px = ((gx + 1.0f) * (float)W0 - 1.0f) * 0.5f;
        float py = ((gy + 1.0f) * (float)H0 - 1.0f) * 0.5f;
        float x0f = floorf(px), y0f = floorf(py);
        float ax = px - x0f, ay = py - y0f;
        int x0 = (int)x0f, y0 = (int)y0f;
        const uint4* p00 = corner_ptr(g_t0h, x0,     y0,     H0, W0);
        const uint4* p10 = corner_ptr(g_t0h, x0 + 1, y0,     H0, W0);
        const uint4* p01 = corner_ptr(g_t0h, x0,     y0 + 1, H0, W0);
        const uint4* p11 = corner_ptr(g_t0h, x0 + 1, y0 + 1, H0, W0);
        uint4 v00a = __ldg(p00), v00b = __ldg(p00 + 1);
        uint4 v10a = __ldg(p10), v10b = __ldg(p10 + 1);
        uint4 v01a = __ldg(p01), v01b = __ldg(p01 + 1);
        uint4 v11a = __ldg(p11), v11b = __ldg(p11 + 1);
        __half2 h00 = __float2half2_rn(corner_w(x0,     y0,     H0, W0, (1.0f - ax) * (1.0f - ay)));
        __half2 h10 = __float2half2_rn(corner_w(x0 + 1, y0,     H0, W0, ax          * (1.0f - ay)));
        __half2 h01 = __float2half2_rn(corner_w(x0,     y0 + 1, H0, W0, (1.0f - ax) * ay));
        __half2 h11 = __float2half2_rn(corner_w(x0 + 1, y0 + 1, H0, W0, ax          * ay));
        accum_texel(v00a, v00b, h00, emb8);
        accum_texel(v10a, v10b, h10, emb8);
        accum_texel(v01a, v01b, h01, emb8);
        accum_texel(v11a, v11b, h11, emb8);
    }

    // ---- consume m1 ----
    accum_texel(u00a, u00b, __float2half2_rn(m1w00), emb8);
    accum_texel(u10a, u10b, __float2half2_rn(m1w10), emb8);
    accum_texel(u01a, u01b, __float2half2_rn(m1w01), emb8);
    accum_texel(u11a, u11b, __float2half2_rn(m1w11), emb8);

    // broadcast each channel into a half2
    __half2 eb[16];
    #pragma unroll
    for (int t = 0; t < 8; ++t) {
        eb[2 * t]     = __low2half2(emb8[t]);
        eb[2 * t + 1] = __high2half2(emb8[t]);
    }

    // --- MLP: h = relu(emb @ w1) in HFMA2; out = softplus(h @ w2) in fp32 ---
    float a0 = 0.0f, a1 = 0.0f, a2 = 0.0f;
    const __half2 zero = __float2half2_rn(0.0f);
    #pragma unroll
    for (int q = 0; q < 16; ++q) {         // 8 hidden units per iteration
        __half2 h0 = zero, h1 = zero, h2v = zero, h3 = zero;
        #pragma unroll
        for (int k = 0; k < 16; ++k) {
            uint4 wv = s_w1u[k * 16 + q];
            const __half2* wh = (const __half2*)&wv;
            h0  = __hfma2(eb[k], wh[0], h0);
            h1  = __hfma2(eb[k], wh[1], h1);
            h2v = __hfma2(eb[k], wh[2], h2v);
            h3  = __hfma2(eb[k], wh[3], h3);
        }
        h0  = __hmax2(h0, zero);
        h1  = __hmax2(h1, zero);
        h2v = __hmax2(h2v, zero);
        h3  = __hmax2(h3, zero);
        float2 f0 = __half22float2(h0);
        float2 f1 = __half22float2(h1);
        float2 f2 = __half22float2(h2v);
        float2 f3 = __half22float2(h3);
        float4 wa0 = s_w2v[2 * q],      wa1 = s_w2v[2 * q + 1];
        float4 wb0 = s_w2v[32 + 2 * q], wb1 = s_w2v[32 + 2 * q + 1];
        float4 wc0 = s_w2v[64 + 2 * q], wc1 = s_w2v[64 + 2 * q + 1];
        a0 = fmaf(f0.x, wa0.x, fmaf(f0.y, wa0.y, fmaf(f1.x, wa0.z, fmaf(f1.y, wa0.w, a0))));
        a0 = fmaf(f2.x, wa1.x, fmaf(f2.y, wa1.y, fmaf(f3.x, wa1.z, fmaf(f3.y, wa1.w, a0))));
        a1 = fmaf(f0.x, wb0.x, fmaf(f0.y, wb0.y, fmaf(f1.x, wb0.z, fmaf(f1.y, wb0.w, a1))));
        a1 = fmaf(f2.x, wb1.x, fmaf(f2.y, wb1.y, fmaf(f3.x, wb1.z, fmaf(f3.y, wb1.w, a1))));
        a2 = fmaf(f0.x, wc0.x, fmaf(f0.y, wc0.y, fmaf(f1.x, wc0.z, fmaf(f1.y, wc0.w, a2))));
        a2 = fmaf(f2.x, wc1.x, fmaf(f2.y, wc1.y, fmaf(f3.x, wc1.z, fmaf(f3.y, wc1.w, a2))));
    }

    out[3 * i + 0] = softplusf(a0);
    out[3 * i + 1] = softplusf(a1);
    out[3 * i + 2] = softplusf(a2);
}

extern "C" void kernel_launch(void* const* d_in, const int* in_sizes, int n_in,
                              void* d_out, int out_size) {
    const float* vd = (const float*)d_in[0];   // viewdirs (B,3)
    const float* m0 = (const float*)d_in[1];   // bg_mat0 (1,16,512,1024)
    const float* m1 = (const float*)d_in[2];   // bg_mat1 (1,16,2048,4096)
    const float* w1 = (const float*)d_in[3];   // (16,128)
    const float* w2 = (const float*)d_in[4];   // (128,3)
    float* out = (float*)d_out;

    __half* t0;
    __half* t1;
    cudaGetSymbolAddress((void**)&t0, g_t0h);
    cudaGetSymbolAddress((void**)&t1, g_t1h);

    const int HW0 = H0 * W0;
    const int HW1 = H1 * W1;
    // m1 first (streamed writes, bypass L2), m0 last (L2-resident for gather)
    transpose_kernel<<<HW1 / 4 / 256, 256>>>(m1, t1, HW1, 1);
    transpose_kernel<<<HW0 / 4 / 256, 256>>>(m0, t0, HW0, 0);

    int n = in_sizes[0] / 3;
    const int threads = 256;
    int blocks = (n + threads - 1) / threads;
    hierarchical_bg_kernel<<<blocks, threads>>>(vd, w1, w2, out, n);
}